// round 2
// baseline (speedup 1.0000x reference)
#include <cuda_runtime.h>

#define FULLMASK 0xffffffffu

typedef unsigned long long u64;

__device__ __forceinline__ float silu_f(float x) {
    return x / (1.0f + __expf(-x));
}

__device__ __forceinline__ u64 pack2(float a, float b) {
    u64 r; asm("mov.b64 %0, {%1,%2};" : "=l"(r) : "f"(a), "f"(b)); return r;
}
__device__ __forceinline__ void unpack2(u64 v, float& a, float& b) {
    asm("mov.b64 {%0,%1}, %2;" : "=f"(a), "=f"(b) : "l"(v));
}
__device__ __forceinline__ u64 ffma2(u64 a, u64 b, u64 c) {
    u64 d; asm("fma.rn.f32x2 %0, %1, %2, %3;" : "=l"(d) : "l"(a), "l"(b), "l"(c));
    return d;
}

// ---------------------------------------------------------------------------
// Edge kernel (f32x2 packed): one filter net over all edges.
// One warp handles 8 edges at a time; lane owns 4 consecutive output columns
// held as 2 f32x2 packs. Broadcast activations (rbf / h1 / e1) are staged in
// smem pre-duplicated as (h,h) u64 pairs so the mainloop is pure
// LDS.128 + fma.rn.f32x2 with no repacking.
// ---------------------------------------------------------------------------
__global__ __launch_bounds__(384, 1)
void edge_filter_kernel(const float* __restrict__ evf,
                        const int*   __restrict__ senders,
                        const int*   __restrict__ receivers,
                        const float* __restrict__ lengths,
                        const float* __restrict__ wr1, const float* __restrict__ br1,
                        const float* __restrict__ wr2, const float* __restrict__ br2,
                        const float* __restrict__ we1, const float* __restrict__ be1,
                        const float* __restrict__ we2, const float* __restrict__ be2,
                        float* __restrict__ outw, int E)
{
    extern __shared__ char smraw[];
    float* wr1s = (float*)smraw;         // 32*128  = 4096
    float* wr2s = wr1s + 4096;           // 128*128 = 16384
    float* we2s = wr2s + 16384;          // 32*128  = 4096
    float* we1s = we2s + 4096;           // 128
    float* br1s = we1s + 128;            // 128
    float* br2s = br1s + 128;            // 128
    float* be2s = br2s + 128;            // 128
    float* be1s = be2s + 128;            // 32
    // u64 region starts at float offset 25120 (byte 100480, 16B aligned)
    u64* dupbase = (u64*)(smraw + 100480);
    // per warp: h1dup[8*128] + sdup[8*32]  = 1280 u64 = 10KB

    const int tid = threadIdx.x;
    for (int i = tid; i < 4096;  i += 384) wr1s[i] = wr1[i];
    for (int i = tid; i < 16384; i += 384) wr2s[i] = wr2[i];
    for (int i = tid; i < 4096;  i += 384) we2s[i] = we2[i];
    if (tid < 128) { we1s[tid] = we1[tid]; br1s[tid] = br1[tid];
                     br2s[tid] = br2[tid]; be2s[tid] = be2[tid]; }
    if (tid < 32)  be1s[tid] = be1[tid];
    __syncthreads();

    const int lane = tid & 31;
    const int warp = tid >> 5;
    u64* h1dup = dupbase + warp * 1280;
    u64* sdup  = h1dup + 1024;

    const int c0 = lane * 4;
    const float4 br1v = *(const float4*)&br1s[c0];
    const float4 br2v = *(const float4*)&br2s[c0];
    const float4 be2v = *(const float4*)&be2s[c0];
    const float  be1v = be1s[lane];
    float we1l[4];
    #pragma unroll
    for (int q = 0; q < 4; q++) we1l[q] = we1s[q * 32 + lane];

    const float center = (float)lane * (5.0f / 31.0f);
    const float GAMMA  = 0.5f * (31.0f / 5.0f) * (31.0f / 5.0f);
    const int SEG[16] = {0,1,1,1,2,2,2,2,2,3,3,3,3,3,3,3};

    const int nGroups = (E + 7) >> 3;
    const int gstride = gridDim.x * 12;

    for (int g = blockIdx.x * 12 + warp; g < nGroups; g += gstride) {
        const int ebase = g * 8;

        int   sI[8], rI[8];
        float dI[8];
        #pragma unroll
        for (int ei = 0; ei < 8; ei++) {
            int e  = ebase + ei;
            int ee = (e < E) ? e : (E - 1);
            sI[ei] = senders[ee];
            rI[ei] = receivers[ee];
            dI[ei] = lengths[ee];
        }

        // ev_diff invariants: 4 seg-sums per edge, broadcast to all lanes
        float inv[8][4];
        #pragma unroll
        for (int ei = 0; ei < 8; ei++) {
            float p = 0.0f;
            if (lane < 16) {
                float a = evf[sI[ei] * 16 + lane] - evf[rI[ei] * 16 + lane];
                p = a * a;
            }
            float s0 = 0.f, s1 = 0.f, s2 = 0.f, s3 = 0.f;
            #pragma unroll
            for (int k = 0; k < 16; k++) {
                float v = __shfl_sync(FULLMASK, p, k);
                if (SEG[k] == 0) s0 += v;
                else if (SEG[k] == 1) s1 += v;
                else if (SEG[k] == 2) s2 += v;
                else s3 += v;
            }
            inv[ei][0] = s0; inv[ei][1] = s1; inv[ei][2] = s2; inv[ei][3] = s3;
        }

        // rbf: lane j holds rbf_j; e1: lane holds col `lane`
        float rbf[8], e1r[8];
        #pragma unroll
        for (int ei = 0; ei < 8; ei++) {
            float t = dI[ei] - center;
            rbf[ei] = __expf(-GAMMA * t * t);
            float a = be1v;
            #pragma unroll
            for (int q = 0; q < 4; q++) a = fmaf(inv[ei][q], we1l[q], a);
            e1r[ei] = silu_f(a);
        }

        // stage rbf duplicated into sdup
        #pragma unroll
        for (int ei = 0; ei < 8; ei++)
            sdup[ei * 32 + lane] = pack2(rbf[ei], rbf[ei]);
        __syncwarp();

        // stage 1: h1 = silu(rbf @ wr1 + br1)   (K=32)
        u64 a1[8][2];
        #pragma unroll
        for (int ei = 0; ei < 8; ei++) {
            a1[ei][0] = pack2(br1v.x, br1v.y);
            a1[ei][1] = pack2(br1v.z, br1v.w);
        }
        #pragma unroll 4
        for (int j = 0; j < 32; j += 2) {
            ulonglong2 wA = *(const ulonglong2*)&wr1s[j * 128 + c0];
            ulonglong2 wB = *(const ulonglong2*)&wr1s[(j + 1) * 128 + c0];
            #pragma unroll
            for (int ei = 0; ei < 8; ei++) {
                ulonglong2 h2 = *(const ulonglong2*)&sdup[ei * 32 + j];
                a1[ei][0] = ffma2(h2.x, wA.x, a1[ei][0]);
                a1[ei][1] = ffma2(h2.x, wA.y, a1[ei][1]);
                a1[ei][0] = ffma2(h2.y, wB.x, a1[ei][0]);
                a1[ei][1] = ffma2(h2.y, wB.y, a1[ei][1]);
            }
        }
        __syncwarp();

        // write e1 duplicated into sdup (rbf no longer needed)
        #pragma unroll
        for (int ei = 0; ei < 8; ei++)
            sdup[ei * 32 + lane] = pack2(e1r[ei], e1r[ei]);

        // silu + duplicate h1 into h1dup
        #pragma unroll
        for (int ei = 0; ei < 8; ei++) {
            float x0, x1, x2, x3;
            unpack2(a1[ei][0], x0, x1);
            unpack2(a1[ei][1], x2, x3);
            float h0 = silu_f(x0), h1v = silu_f(x1);
            float h2v = silu_f(x2), h3v = silu_f(x3);
            ulonglong2 s0, s1;
            s0.x = pack2(h0, h0);   s0.y = pack2(h1v, h1v);
            s1.x = pack2(h2v, h2v); s1.y = pack2(h3v, h3v);
            *(ulonglong2*)&h1dup[ei * 128 + c0]     = s0;
            *(ulonglong2*)&h1dup[ei * 128 + c0 + 2] = s1;
        }
        __syncwarp();

        // stage 2: h2pre = h1 @ wr2 + br2   (K=128)
        u64 a2[8][2];
        #pragma unroll
        for (int ei = 0; ei < 8; ei++) {
            a2[ei][0] = pack2(br2v.x, br2v.y);
            a2[ei][1] = pack2(br2v.z, br2v.w);
        }
        #pragma unroll 4
        for (int j = 0; j < 128; j += 2) {
            ulonglong2 wA = *(const ulonglong2*)&wr2s[j * 128 + c0];
            ulonglong2 wB = *(const ulonglong2*)&wr2s[(j + 1) * 128 + c0];
            #pragma unroll
            for (int ei = 0; ei < 8; ei++) {
                ulonglong2 h2 = *(const ulonglong2*)&h1dup[ei * 128 + j];
                a2[ei][0] = ffma2(h2.x, wA.x, a2[ei][0]);
                a2[ei][1] = ffma2(h2.x, wA.y, a2[ei][1]);
                a2[ei][0] = ffma2(h2.y, wB.x, a2[ei][0]);
                a2[ei][1] = ffma2(h2.y, wB.y, a2[ei][1]);
            }
        }

        // silu(stage2) into floats
        float o2[8][4];
        #pragma unroll
        for (int ei = 0; ei < 8; ei++) {
            float x0, x1, x2, x3;
            unpack2(a2[ei][0], x0, x1);
            unpack2(a2[ei][1], x2, x3);
            o2[ei][0] = silu_f(x0); o2[ei][1] = silu_f(x1);
            o2[ei][2] = silu_f(x2); o2[ei][3] = silu_f(x3);
        }

        // stage E: e2pre = e1 @ we2 + be2   (K=32)
        u64 aE[8][2];
        #pragma unroll
        for (int ei = 0; ei < 8; ei++) {
            aE[ei][0] = pack2(be2v.x, be2v.y);
            aE[ei][1] = pack2(be2v.z, be2v.w);
        }
        #pragma unroll 4
        for (int j = 0; j < 32; j += 2) {
            ulonglong2 wA = *(const ulonglong2*)&we2s[j * 128 + c0];
            ulonglong2 wB = *(const ulonglong2*)&we2s[(j + 1) * 128 + c0];
            #pragma unroll
            for (int ei = 0; ei < 8; ei++) {
                ulonglong2 h2 = *(const ulonglong2*)&sdup[ei * 32 + j];
                aE[ei][0] = ffma2(h2.x, wA.x, aE[ei][0]);
                aE[ei][1] = ffma2(h2.x, wA.y, aE[ei][1]);
                aE[ei][0] = ffma2(h2.y, wB.x, aE[ei][0]);
                aE[ei][1] = ffma2(h2.y, wB.y, aE[ei][1]);
            }
        }

        // out = silu(stage2) + silu(stageE)
        #pragma unroll
        for (int ei = 0; ei < 8; ei++) {
            int e = ebase + ei;
            if (e < E) {
                float y0, y1, y2, y3;
                unpack2(aE[ei][0], y0, y1);
                unpack2(aE[ei][1], y2, y3);
                float4 o;
                o.x = o2[ei][0] + silu_f(y0);
                o.y = o2[ei][1] + silu_f(y1);
                o.z = o2[ei][2] + silu_f(y2);
                o.w = o2[ei][3] + silu_f(y3);
                *(float4*)&outw[(size_t)e * 128 + c0] = o;
            }
        }
        __syncwarp();
    }
}

// ---------------------------------------------------------------------------
// Node kernel (unchanged from round 1): 134us, ~5% of total.
// ---------------------------------------------------------------------------
__global__ __launch_bounds__(264, 2)
void node_kernel(const float* __restrict__ inv_f, const float* __restrict__ ev_f,
                 const float* __restrict__ w_int, const float* __restrict__ b_int,
                 float* __restrict__ out_inv, float* __restrict__ out_ev, int N)
{
    extern __shared__ float sm[];
    float* Wsh = sm;                 // 132*132 = 17424
    float* bsh = Wsh + 17424;        // 132
    float* xs  = bsh + 132;          // 32*132 = 4224
    float* aev = xs + 4224;          // 32*16  = 512

    const int tx  = threadIdx.x;     // 0..32
    const int ty  = threadIdx.y;     // 0..7
    const int tid = tx + 33 * ty;
    const int NT  = 264;

    for (int i = tid; i < 17424; i += NT) Wsh[i] = w_int[i];
    if (tid < 132) bsh[tid] = b_int[tid];
    __syncthreads();

    const int nTiles = (N + 31) / 32;
    for (int tile = blockIdx.x; tile < nTiles; tile += gridDim.x) {
        const int base = tile * 32;

        for (int i = tid; i < 32 * 132; i += NT) {
            int l = i / 132, c = i % 132;
            int n = base + l;
            float v = 0.0f;
            if (n < N) {
                if (c < 128) {
                    v = 2.0f * inv_f[(size_t)n * 128 + c];
                } else {
                    const int st[5] = {0, 1, 4, 9, 16};
                    int s = c - 128;
                    float acc = 0.0f;
                    for (int k = st[s]; k < st[s + 1]; k++) {
                        float a = 2.0f * ev_f[(size_t)n * 16 + k];
                        acc = fmaf(a, a, acc);
                    }
                    v = acc;
                }
            }
            xs[l * 132 + c] = v;
        }
        for (int i = tid; i < 512; i += NT) {
            int l = i / 16, k = i % 16;
            int n = base + l;
            aev[i] = (n < N) ? 2.0f * ev_f[(size_t)n * 16 + k] : 0.0f;
        }
        __syncthreads();

        const int c0 = tx * 4;
        float acc[4][4];
        #pragma unroll
        for (int i = 0; i < 4; i++)
            #pragma unroll
            for (int k = 0; k < 4; k++) acc[i][k] = 0.0f;

        #pragma unroll 4
        for (int j = 0; j < 132; j++) {
            float4 w4 = *(const float4*)&Wsh[j * 132 + c0];
            #pragma unroll
            for (int i = 0; i < 4; i++) {
                float xv = xs[(ty * 4 + i) * 132 + j];
                acc[i][0] = fmaf(xv, w4.x, acc[i][0]);
                acc[i][1] = fmaf(xv, w4.y, acc[i][1]);
                acc[i][2] = fmaf(xv, w4.z, acc[i][2]);
                acc[i][3] = fmaf(xv, w4.w, acc[i][3]);
            }
        }

        const float4 bv = *(const float4*)&bsh[c0];
        #pragma unroll
        for (int i = 0; i < 4; i++) {
            int n = base + ty * 4 + i;
            if (n >= N) continue;
            float t0 = acc[i][0] + bv.x;
            float t1 = acc[i][1] + bv.y;
            float t2 = acc[i][2] + bv.z;
            float t3 = acc[i][3] + bv.w;
            if (tx < 32) {
                float4 o;
                o.x = xs[(ty * 4 + i) * 132 + c0 + 0] + t0;
                o.y = xs[(ty * 4 + i) * 132 + c0 + 1] + t1;
                o.z = xs[(ty * 4 + i) * 132 + c0 + 2] + t2;
                o.w = xs[(ty * 4 + i) * 132 + c0 + 3] + t3;
                *(float4*)&out_inv[(size_t)n * 128 + c0] = o;
            } else {
                float tb[4] = {t0, t1, t2, t3};
                const int SEG[16] = {0,1,1,1,2,2,2,2,2,3,3,3,3,3,3,3};
                #pragma unroll
                for (int k = 0; k < 16; k++) {
                    out_ev[(size_t)n * 16 + k] =
                        aev[(ty * 4 + i) * 16 + k] * (1.0f + tb[SEG[k]]);
                }
            }
        }
        __syncthreads();
    }
}

// ---------------------------------------------------------------------------
// Launch
// ---------------------------------------------------------------------------
static const int EDGE_SMEM = 100480 + 12 * 1280 * 8;   // 100480 + 122880 = 223360 B
static const int NODE_SMEM = 22292 * 4;                // 89168 B

extern "C" void kernel_launch(void* const* d_in, const int* in_sizes, int n_in,
                              void* d_out, int out_size)
{
    const float* inv_f     = (const float*)d_in[0];
    const float* ev_f      = (const float*)d_in[1];
    const int*   senders   = (const int*)  d_in[2];
    const int*   receivers = (const int*)  d_in[3];
    const float* lengths   = (const float*)d_in[5];

    const float* fi_rbf_w1 = (const float*)d_in[7];
    const float* fi_rbf_b1 = (const float*)d_in[8];
    const float* fi_rbf_w2 = (const float*)d_in[9];
    const float* fi_rbf_b2 = (const float*)d_in[10];
    const float* fi_ev_w1  = (const float*)d_in[11];
    const float* fi_ev_b1  = (const float*)d_in[12];
    const float* fi_ev_w2  = (const float*)d_in[13];
    const float* fi_ev_b2  = (const float*)d_in[14];
    const float* fe_rbf_w1 = (const float*)d_in[15];
    const float* fe_rbf_b1 = (const float*)d_in[16];
    const float* fe_rbf_w2 = (const float*)d_in[17];
    const float* fe_rbf_b2 = (const float*)d_in[18];
    const float* fe_ev_w1  = (const float*)d_in[19];
    const float* fe_ev_b1  = (const float*)d_in[20];
    const float* fe_ev_w2  = (const float*)d_in[21];
    const float* fe_ev_b2  = (const float*)d_in[22];
    const float* w_int     = (const float*)d_in[23];
    const float* b_int     = (const float*)d_in[24];

    const int N = in_sizes[0] / 128;
    const int E = in_sizes[2];

    float* out     = (float*)d_out;
    float* out_inv = out;
    float* out_ev  = out + (size_t)N * 128;
    float* fw_inv  = out + (size_t)N * 144;
    float* fw_ev   = fw_inv + (size_t)E * 128;

    cudaFuncSetAttribute(node_kernel,
                         cudaFuncAttributeMaxDynamicSharedMemorySize, NODE_SMEM);
    cudaFuncSetAttribute(edge_filter_kernel,
                         cudaFuncAttributeMaxDynamicSharedMemorySize, EDGE_SMEM);

    node_kernel<<<304, dim3(33, 8), NODE_SMEM>>>(
        inv_f, ev_f, w_int, b_int, out_inv, out_ev, N);

    edge_filter_kernel<<<148, 384, EDGE_SMEM>>>(
        ev_f, senders, receivers, lengths,
        fi_rbf_w1, fi_rbf_b1, fi_rbf_w2, fi_rbf_b2,
        fi_ev_w1,  fi_ev_b1,  fi_ev_w2,  fi_ev_b2,
        fw_inv, E);

    edge_filter_kernel<<<148, 384, EDGE_SMEM>>>(
        ev_f, senders, receivers, lengths,
        fe_rbf_w1, fe_rbf_b1, fe_rbf_w2, fe_rbf_b2,
        fe_ev_w1,  fe_ev_b1,  fe_ev_w2,  fe_ev_b2,
        fw_ev, E);
}